// round 2
// baseline (speedup 1.0000x reference)
#include <cuda_runtime.h>
#include <math.h>

#define BB 64
#define LL 1024
#define DD 512
#define HH 1024
#define GG 4096          // 4*HH
#define NCTA 128         // phase-2 persistent CTAs (<= 148 SMs, all co-resident)

// ---------------- scratch (static device allocations only) ----------------
static __device__ float    g_gx[(size_t)LL * BB * GG];   // [t][b][4H]  (1 GiB)
static __device__ float    g_hbuf[2][BB * HH];
static __device__ float    g_cbuf[BB * HH];
static __device__ unsigned g_bar[LL];                    // one counter per step
static __device__ int      g_mask_mode;                  // 0=byte 1=int32 2=float32

// ---------------- init: zero state + barrier counters, probe mask dtype ----
__global__ void init_kernel(const void* mask)
{
    int i = blockIdx.x * blockDim.x + threadIdx.x;
    if (i < BB * HH) { g_hbuf[0][i] = 0.0f; g_cbuf[i] = 0.0f; }
    if (i < LL)      { g_bar[i] = 0u; }
    if (i == 0) {
        // lengths >= L/2 = 512, so mask[0, 0..3] are all True.
        int v = *(const int*)mask;
        if (v == 1)                 g_mask_mode = 1;   // int32 0/1
        else if (v == 0x3F800000)   g_mask_mode = 2;   // float32 0/1
        else                        g_mask_mode = 0;   // 1-byte bool
    }
}

// ---------------- phase 1: g_gx[t][b][n] = X @ W_ih^T + b_ih + b_hh --------
// C[m,n] = sum_k X[m,k] * Wih[n,k],  m = b*L + t.  Stored transposed to [t][b][n].
__global__ __launch_bounds__(256)
void gemm_x_kernel(const float* __restrict__ X, const float* __restrict__ W,
                   const float* __restrict__ bih, const float* __restrict__ bhh)
{
    __shared__ __align__(16) float As[2][16][128];
    __shared__ __align__(16) float Bs[2][16][128];

    const int tid = threadIdx.x;
    const int tx  = tid & 15;        // 0..15 (col groups of 8)
    const int ty  = tid >> 4;        // 0..15 (row groups of 8)
    const int m0  = blockIdx.y * 128;
    const int n0  = blockIdx.x * 128;

    float acc[8][8];
#pragma unroll
    for (int i = 0; i < 8; i++)
#pragma unroll
        for (int j = 0; j < 8; j++) acc[i][j] = 0.0f;

    const int ia0 = tid;             // float4 slot 0..255
    const int ia1 = tid + 256;       // float4 slot 256..511
    const int r0a = ia0 >> 2, kc0 = (ia0 & 3) << 2;
    const int r1a = ia1 >> 2, kc1 = (ia1 & 3) << 2;

    float4 ra0, ra1, rb0, rb1;
    ra0 = *(const float4*)(X + (size_t)(m0 + r0a) * DD + kc0);
    ra1 = *(const float4*)(X + (size_t)(m0 + r1a) * DD + kc1);
    rb0 = *(const float4*)(W + (size_t)(n0 + r0a) * DD + kc0);
    rb1 = *(const float4*)(W + (size_t)(n0 + r1a) * DD + kc1);

    int buf = 0;
    for (int kt = 0; kt < DD; kt += 16) {
        As[buf][kc0 + 0][r0a] = ra0.x; As[buf][kc0 + 1][r0a] = ra0.y;
        As[buf][kc0 + 2][r0a] = ra0.z; As[buf][kc0 + 3][r0a] = ra0.w;
        As[buf][kc1 + 0][r1a] = ra1.x; As[buf][kc1 + 1][r1a] = ra1.y;
        As[buf][kc1 + 2][r1a] = ra1.z; As[buf][kc1 + 3][r1a] = ra1.w;
        Bs[buf][kc0 + 0][r0a] = rb0.x; Bs[buf][kc0 + 1][r0a] = rb0.y;
        Bs[buf][kc0 + 2][r0a] = rb0.z; Bs[buf][kc0 + 3][r0a] = rb0.w;
        Bs[buf][kc1 + 0][r1a] = rb1.x; Bs[buf][kc1 + 1][r1a] = rb1.y;
        Bs[buf][kc1 + 2][r1a] = rb1.z; Bs[buf][kc1 + 3][r1a] = rb1.w;
        __syncthreads();

        if (kt + 16 < DD) {
            ra0 = *(const float4*)(X + (size_t)(m0 + r0a) * DD + kt + 16 + kc0);
            ra1 = *(const float4*)(X + (size_t)(m0 + r1a) * DD + kt + 16 + kc1);
            rb0 = *(const float4*)(W + (size_t)(n0 + r0a) * DD + kt + 16 + kc0);
            rb1 = *(const float4*)(W + (size_t)(n0 + r1a) * DD + kt + 16 + kc1);
        }

#pragma unroll
        for (int kk = 0; kk < 16; kk++) {
            float a0[8], b0[8];
            *(float4*)(&a0[0]) = *(const float4*)(&As[buf][kk][ty * 8]);
            *(float4*)(&a0[4]) = *(const float4*)(&As[buf][kk][ty * 8 + 4]);
            *(float4*)(&b0[0]) = *(const float4*)(&Bs[buf][kk][tx * 8]);
            *(float4*)(&b0[4]) = *(const float4*)(&Bs[buf][kk][tx * 8 + 4]);
#pragma unroll
            for (int i = 0; i < 8; i++)
#pragma unroll
                for (int j = 0; j < 8; j++) acc[i][j] += a0[i] * b0[j];
        }
        buf ^= 1;
    }

    float bias[8];
#pragma unroll
    for (int j = 0; j < 8; j++) {
        int n = n0 + tx * 8 + j;
        bias[j] = bih[n] + bhh[n];
    }
#pragma unroll
    for (int rr = 0; rr < 8; rr++) {
        int m = m0 + ty * 8 + rr;
        int b = m >> 10;        // /L
        int t = m & 1023;       // %L
        float* dst = g_gx + ((size_t)t * BB + b) * GG + n0 + tx * 8;
        float4 v0, v1;
        v0.x = acc[rr][0] + bias[0]; v0.y = acc[rr][1] + bias[1];
        v0.z = acc[rr][2] + bias[2]; v0.w = acc[rr][3] + bias[3];
        v1.x = acc[rr][4] + bias[4]; v1.y = acc[rr][5] + bias[5];
        v1.z = acc[rr][6] + bias[6]; v1.w = acc[rr][7] + bias[7];
        *(float4*)(dst)     = v0;
        *(float4*)(dst + 4) = v1;
    }
}

// ---------------- phase 2: persistent sequential LSTM steps ----------------
// CTA j owns h-columns [j*8, j*8+8). Per step it computes the 64x32 gate slab
// (4 gates x 8 h-cols) = Hold(64x1024) @ Whh_slice^T, then the elementwise
// cell update for its columns. h is double-buffered; c is CTA-private.
__device__ __forceinline__ float sigmoidf_(float x) {
    return 1.0f / (1.0f + expf(-x));
}

__global__ __launch_bounds__(128)
void lstm_kernel(const float* __restrict__ Whh,
                 const unsigned char* __restrict__ m8,
                 const int* __restrict__ m32,
                 const float* __restrict__ mf,
                 const float* __restrict__ wci,
                 const float* __restrict__ wcf,
                 const float* __restrict__ wco,
                 float* __restrict__ out)
{
    __shared__ __align__(16) float As[2][16][64];
    __shared__ __align__(16) float Bs[2][16][32];
    __shared__ __align__(16) float Gs[64][33];
    __shared__ float s_wci[8], s_wcf[8], s_wco[8];

    const int tid = threadIdx.x;
    const int tx  = tid & 7;         // 0..7  (col groups of 4)
    const int ty  = tid >> 3;        // 0..15 (row groups of 4)
    const int cta = blockIdx.x;
    const int h0  = cta * 8;
    const int r0  = ty * 4;
    const int c0  = tx * 4;

    if (tid < 8) {
        s_wci[tid] = wci[h0 + tid];
        s_wcf[tid] = wcf[h0 + tid];
        s_wco[tid] = wco[h0 + tid];
    }
    __syncthreads();
    const int mmode = g_mask_mode;

    // B-tile loader mapping: thread -> (cc, kc) of the 32x16 W tile
    const int bcc = tid >> 2;                      // 0..31 gate-col within CTA
    const int bkc = (tid & 3) << 2;                // 0,4,8,12
    const int brow = (bcc >> 3) * HH + h0 + (bcc & 7);   // W_hh row (gate col)
    const float* wptr = Whh + (size_t)brow * HH + bkc;

    // A-tile loader mapping: two float4 slots per thread over 64x16
    const int ia0 = tid, ia1 = tid + 128;
    const int ar0 = ia0 >> 2, akc0 = (ia0 & 3) << 2;
    const int ar1 = ia1 >> 2, akc1 = (ia1 & 3) << 2;

    // acc column -> global gate column base (4 consecutive cols in one gate)
    const int ggate = c0 >> 3;
    const int nacc  = ggate * HH + h0 + (c0 & 7);

    for (int t = 0; t < LL; ++t) {
        const float* hb = g_hbuf[t & 1];
        float*       hn = g_hbuf[(t + 1) & 1];
        const float* gx = g_gx + (size_t)t * (BB * GG);

        // init accumulators from precomputed x-projection (+ biases)
        float acc[4][4];
#pragma unroll
        for (int rr = 0; rr < 4; rr++) {
            float4 v = *(const float4*)(gx + (size_t)(r0 + rr) * GG + nacc);
            acc[rr][0] = v.x; acc[rr][1] = v.y; acc[rr][2] = v.z; acc[rr][3] = v.w;
        }

        // prefetch k-tile 0 (h via L2-coherent loads; Whh via normal loads)
        float4 ra0 = __ldcg((const float4*)(hb + ar0 * HH + akc0));
        float4 ra1 = __ldcg((const float4*)(hb + ar1 * HH + akc1));
        float4 rb  = *(const float4*)(wptr);

        int buf = 0;
        for (int kt = 0; kt < HH; kt += 16) {
            As[buf][akc0 + 0][ar0] = ra0.x; As[buf][akc0 + 1][ar0] = ra0.y;
            As[buf][akc0 + 2][ar0] = ra0.z; As[buf][akc0 + 3][ar0] = ra0.w;
            As[buf][akc1 + 0][ar1] = ra1.x; As[buf][akc1 + 1][ar1] = ra1.y;
            As[buf][akc1 + 2][ar1] = ra1.z; As[buf][akc1 + 3][ar1] = ra1.w;
            Bs[buf][bkc + 0][bcc]  = rb.x;  Bs[buf][bkc + 1][bcc]  = rb.y;
            Bs[buf][bkc + 2][bcc]  = rb.z;  Bs[buf][bkc + 3][bcc]  = rb.w;
            __syncthreads();

            if (kt + 16 < HH) {
                ra0 = __ldcg((const float4*)(hb + ar0 * HH + kt + 16 + akc0));
                ra1 = __ldcg((const float4*)(hb + ar1 * HH + kt + 16 + akc1));
                rb  = *(const float4*)(wptr + kt + 16);
            }

#pragma unroll
            for (int kk = 0; kk < 16; kk++) {
                float4 av = *(const float4*)(&As[buf][kk][r0]);
                float4 bv = *(const float4*)(&Bs[buf][kk][c0]);
                float aa[4] = {av.x, av.y, av.z, av.w};
                float bb[4] = {bv.x, bv.y, bv.z, bv.w};
#pragma unroll
                for (int i = 0; i < 4; i++)
#pragma unroll
                    for (int j = 0; j < 4; j++) acc[i][j] += aa[i] * bb[j];
            }
            buf ^= 1;
        }

        // exchange gates through smem (i/f/g/o for one h-idx live in 4 threads)
#pragma unroll
        for (int rr = 0; rr < 4; rr++)
#pragma unroll
            for (int c = 0; c < 4; c++)
                Gs[r0 + rr][c0 + c] = acc[rr][c];
        __syncthreads();

        // elementwise cell update: 512 (row, h) pairs, 4 per thread
#pragma unroll
        for (int q = 0; q < 4; q++) {
            int p    = q * 128 + tid;
            int row  = p >> 3;
            int hh   = p & 7;
            int hcol = h0 + hh;

            float zi = Gs[row][hh];
            float zf = Gs[row][8 + hh];
            float zg = Gs[row][16 + hh];
            float zo = Gs[row][24 + hh];

            float cold = g_cbuf[row * HH + hcol];
            float iv = sigmoidf_(zi + s_wci[hh] * cold);
            float fv = sigmoidf_(zf + s_wcf[hh] * cold);
            float gv = tanhf(zg);
            float cy = fv * cold + iv * gv;
            float ov = sigmoidf_(zo + s_wco[hh] * cy);
            float hy = ov * tanhf(cy);

            bool mm;
            if (mmode == 1)      mm = (m32[row * LL + t] != 0);
            else if (mmode == 2) mm = (mf[row * LL + t] != 0.0f);
            else                 mm = (m8[row * LL + t] != 0);

            float hold = __ldcg(hb + row * HH + hcol);
            float hnew = mm ? hy : hold;
            float cnew = mm ? cy : cold;

            g_cbuf[row * HH + hcol] = cnew;
            hn[row * HH + hcol]     = hnew;
            out[((size_t)row * LL + t) * HH + hcol] = hnew;
        }

        // grid-wide barrier (all 128 CTAs co-resident; fresh counter per step)
        __syncthreads();
        if (tid == 0) {
            __threadfence();
            atomicAdd(&g_bar[t], 1u);
            while (*(volatile unsigned*)&g_bar[t] < (unsigned)gridDim.x) {
                __nanosleep(64);
            }
            __threadfence();
        }
        __syncthreads();
    }
}

// ---------------- finalize: append h_T and c_T after outs ------------------
__global__ void finalize_kernel(float* __restrict__ out)
{
    int i = blockIdx.x * blockDim.x + threadIdx.x;
    if (i < BB * HH) {
        out[(size_t)BB * LL * HH + i]           = g_hbuf[0][i];  // final h (t=1023 wrote buf 0)
        out[(size_t)BB * LL * HH + BB * HH + i] = g_cbuf[i];
    }
}

// ---------------- launch ---------------------------------------------------
extern "C" void kernel_launch(void* const* d_in, const int* in_sizes, int n_in,
                              void* d_out, int out_size)
{
    (void)in_sizes; (void)n_in; (void)out_size;
    const float* X    = (const float*)d_in[0];
    const void*  mask = d_in[1];
    const float* Wih  = (const float*)d_in[2];
    const float* Whh  = (const float*)d_in[3];
    const float* bih  = (const float*)d_in[4];
    const float* bhh  = (const float*)d_in[5];
    const float* wci  = (const float*)d_in[6];
    const float* wcf  = (const float*)d_in[7];
    const float* wco  = (const float*)d_in[8];
    float* out = (float*)d_out;

    init_kernel<<<256, 256>>>(mask);

    dim3 g1(GG / 128, (BB * LL) / 128);   // (32, 512)
    gemm_x_kernel<<<g1, 256>>>(X, Wih, bih, bhh);

    lstm_kernel<<<NCTA, 128>>>(Whh,
                               (const unsigned char*)mask,
                               (const int*)mask,
                               (const float*)mask,
                               wci, wcf, wco, out);

    finalize_kernel<<<(BB * HH + 255) / 256, 256>>>(out);
}

// round 4
// speedup vs baseline: 1.7877x; 1.7877x over previous
#include <cuda_runtime.h>
#include <cuda_bf16.h>
#include <math.h>
#include <stdint.h>

#define BB 64
#define LL 1024
#define DD 512
#define HH 1024
#define GG 4096
#define NCTA 128
#define NT 256

// dynamic smem layout for lstm kernel
#define SM_BHI 0                     // 32 x 1024 bf16 (swizzled)   64KB
#define SM_BLO 65536                 // lo part                     64KB
#define SM_A   131072                // 2 bufs x (hi 8KB + lo 8KB)  32KB
#define SM_D   163840                // 64 x 36 fp32 gate board     9216B
#define SMEM_TOTAL (SM_D + 64 * 36 * 4)

static __device__ float g_gx[(size_t)LL * BB * GG];   // [t][b][4H]
static __device__ __align__(16) __nv_bfloat16 g_hhi[2][BB * HH];
static __device__ __align__(16) __nv_bfloat16 g_hlo[2][BB * HH];
static __device__ unsigned g_bar[LL];
static __device__ int g_mask_mode;

__device__ __forceinline__ uint32_t smem_u32(const void* p) {
    uint32_t a;
    asm("{ .reg .u64 t; cvta.to.shared.u64 t, %1; cvt.u32.u64 %0, t; }" : "=r"(a) : "l"(p));
    return a;
}
#define LDSM4(r, addr) asm volatile( \
    "ldmatrix.sync.aligned.m8n8.x4.shared.b16 {%0,%1,%2,%3}, [%4];" \
    : "=r"((r)[0]), "=r"((r)[1]), "=r"((r)[2]), "=r"((r)[3]) : "r"(addr))
#define LDSM2(r, addr) asm volatile( \
    "ldmatrix.sync.aligned.m8n8.x2.shared.b16 {%0,%1}, [%2];" \
    : "=r"((r)[0]), "=r"((r)[1]) : "r"(addr))
#define MMA16816(d, a, b) asm volatile( \
    "mma.sync.aligned.m16n8k16.row.col.f32.bf16.bf16.f32 " \
    "{%0,%1,%2,%3}, {%4,%5,%6,%7}, {%8,%9}, {%0,%1,%2,%3};" \
    : "+f"((d)[0]), "+f"((d)[1]), "+f"((d)[2]), "+f"((d)[3]) \
    : "r"((a)[0]), "r"((a)[1]), "r"((a)[2]), "r"((a)[3]), "r"((b)[0]), "r"((b)[1]))

__device__ __forceinline__ float sigf(float x) {
    return 1.0f / (1.0f + __expf(-x));
}
__device__ __forceinline__ float tanhf_fast(float x) {
    float ax = fabsf(x);
    float e = __expf(2.0f * ax);
    float t = 1.0f - 2.0f / (e + 1.0f);       // e->inf => t->1
    return copysignf(t, x);
}

// ---------------- init -------------------------------------------------------
__global__ void init_kernel(const void* mask)
{
    int i = blockIdx.x * blockDim.x + threadIdx.x;
    if (i < BB * HH) {
        g_hhi[0][i] = __float2bfloat16(0.0f);
        g_hlo[0][i] = __float2bfloat16(0.0f);
    }
    if (i < LL) g_bar[i] = 0u;
    if (i == 0) {
        int v = *(const int*)mask;             // lengths >= 512 -> mask[0,0..3] true
        if (v == 1)               g_mask_mode = 1;
        else if (v == 0x3F800000) g_mask_mode = 2;
        else                      g_mask_mode = 0;
    }
}

// ---------------- phase 1: g_gx = X @ Wih^T + b_ih + b_hh (fp32 SIMT) -------
__global__ __launch_bounds__(256)
void gemm_x_kernel(const float* __restrict__ X, const float* __restrict__ W,
                   const float* __restrict__ bih, const float* __restrict__ bhh)
{
    __shared__ __align__(16) float As[2][16][128];
    __shared__ __align__(16) float Bs[2][16][128];
    const int tid = threadIdx.x, tx = tid & 15, ty = tid >> 4;
    const int m0 = blockIdx.y * 128, n0 = blockIdx.x * 128;
    float acc[8][8];
#pragma unroll
    for (int i = 0; i < 8; i++)
#pragma unroll
        for (int j = 0; j < 8; j++) acc[i][j] = 0.0f;
    const int r0a = tid >> 2, kc0 = (tid & 3) << 2;
    const int r1a = (tid + 256) >> 2, kc1 = kc0;
    float4 ra0 = *(const float4*)(X + (size_t)(m0 + r0a) * DD + kc0);
    float4 ra1 = *(const float4*)(X + (size_t)(m0 + r1a) * DD + kc1);
    float4 rb0 = *(const float4*)(W + (size_t)(n0 + r0a) * DD + kc0);
    float4 rb1 = *(const float4*)(W + (size_t)(n0 + r1a) * DD + kc1);
    int buf = 0;
    for (int kt = 0; kt < DD; kt += 16) {
        As[buf][kc0 + 0][r0a] = ra0.x; As[buf][kc0 + 1][r0a] = ra0.y;
        As[buf][kc0 + 2][r0a] = ra0.z; As[buf][kc0 + 3][r0a] = ra0.w;
        As[buf][kc1 + 0][r1a] = ra1.x; As[buf][kc1 + 1][r1a] = ra1.y;
        As[buf][kc1 + 2][r1a] = ra1.z; As[buf][kc1 + 3][r1a] = ra1.w;
        Bs[buf][kc0 + 0][r0a] = rb0.x; Bs[buf][kc0 + 1][r0a] = rb0.y;
        Bs[buf][kc0 + 2][r0a] = rb0.z; Bs[buf][kc0 + 3][r0a] = rb0.w;
        Bs[buf][kc1 + 0][r1a] = rb1.x; Bs[buf][kc1 + 1][r1a] = rb1.y;
        Bs[buf][kc1 + 2][r1a] = rb1.z; Bs[buf][kc1 + 3][r1a] = rb1.w;
        __syncthreads();
        if (kt + 16 < DD) {
            ra0 = *(const float4*)(X + (size_t)(m0 + r0a) * DD + kt + 16 + kc0);
            ra1 = *(const float4*)(X + (size_t)(m0 + r1a) * DD + kt + 16 + kc1);
            rb0 = *(const float4*)(W + (size_t)(n0 + r0a) * DD + kt + 16 + kc0);
            rb1 = *(const float4*)(W + (size_t)(n0 + r1a) * DD + kt + 16 + kc1);
        }
#pragma unroll
        for (int kk = 0; kk < 16; kk++) {
            float a0[8], b0[8];
            *(float4*)(&a0[0]) = *(const float4*)(&As[buf][kk][ty * 8]);
            *(float4*)(&a0[4]) = *(const float4*)(&As[buf][kk][ty * 8 + 4]);
            *(float4*)(&b0[0]) = *(const float4*)(&Bs[buf][kk][tx * 8]);
            *(float4*)(&b0[4]) = *(const float4*)(&Bs[buf][kk][tx * 8 + 4]);
#pragma unroll
            for (int i = 0; i < 8; i++)
#pragma unroll
                for (int j = 0; j < 8; j++) acc[i][j] += a0[i] * b0[j];
        }
        buf ^= 1;
    }
    float bias[8];
#pragma unroll
    for (int j = 0; j < 8; j++) { int n = n0 + tx * 8 + j; bias[j] = bih[n] + bhh[n]; }
#pragma unroll
    for (int rr = 0; rr < 8; rr++) {
        int m = m0 + ty * 8 + rr;
        int b = m >> 10, t = m & 1023;
        float* dst = g_gx + ((size_t)t * BB + b) * GG + n0 + tx * 8;
        float4 v0, v1;
        v0.x = acc[rr][0] + bias[0]; v0.y = acc[rr][1] + bias[1];
        v0.z = acc[rr][2] + bias[2]; v0.w = acc[rr][3] + bias[3];
        v1.x = acc[rr][4] + bias[4]; v1.y = acc[rr][5] + bias[5];
        v1.z = acc[rr][6] + bias[6]; v1.w = acc[rr][7] + bias[7];
        *(float4*)(dst) = v0; *(float4*)(dst + 4) = v1;
    }
}

// ---------------- phase 2: persistent HMMA (mma.sync) recurrence ------------
// CTA owns 8 h-cols -> 32 gate cols. Per step:
//   D[64,32] = h[64,1024] (bf16 hi/lo) @ Wslab^T (bf16 hi/lo), 3-pass fp32 MMA.
// warp w: rows 16*(w&3).. , cols 16*(w>>2)..  (2 n-tiles of 8)
__global__ __launch_bounds__(NT, 1)
void lstm_mma_kernel(const float* __restrict__ Whh,
                     const unsigned char* __restrict__ m8,
                     const int* __restrict__ m32,
                     const float* __restrict__ mf,
                     const float* __restrict__ wci,
                     const float* __restrict__ wcf,
                     const float* __restrict__ wco,
                     float* __restrict__ out)
{
    extern __shared__ __align__(16) char sm[];
    const uint32_t smb = smem_u32(sm);
    float* Ds = (float*)(sm + SM_D);

    const int tid  = threadIdx.x;
    const int lane = tid & 31;
    const int w    = tid >> 5;
    const int h0   = blockIdx.x * 8;

    // ---- one-time: W slab -> smem bf16 hi/lo, row-major 32 x 1024, swizzled
    for (int s = tid; s < 4096; s += NT) {
        int n = s >> 7, c = s & 127;                 // n: local gate col, c: 16B col
        int gr = (n >> 3) * HH + h0 + (n & 7);       // W_hh row
        const float* wp = Whh + (size_t)gr * HH + c * 8;
        __align__(16) __nv_bfloat16 hi8[8], lo8[8];
#pragma unroll
        for (int j = 0; j < 8; j++) {
            float wv = wp[j];
            __nv_bfloat16 hb = __float2bfloat16(wv);
            hi8[j] = hb;
            lo8[j] = __float2bfloat16(wv - __bfloat162float(hb));
        }
        int off = n * 2048 + ((c ^ (n & 7)) << 4);
        *(uint4*)(sm + SM_BHI + off) = *(uint4*)hi8;
        *(uint4*)(sm + SM_BLO + off) = *(uint4*)lo8;
    }
    __syncthreads();

    // ---- per-warp mma geometry
    const int m0  = (w & 3) << 4;                    // row tile
    const int n0w = (w >> 2) << 4;                   // col tile (2 n-subtiles)
    const int seg = lane >> 3, rr = lane & 7;
    const int arow = m0 + ((seg & 1) << 3) + rr;     // A ldmatrix row
    const int adk  = seg >> 1;                       // A k-half
    const int a_row_off = arow * 128;
    const int ax = arow & 7;
    const int bseg  = seg & 1;                       // B k-half (x2 uses lanes 0-15)
    const int brow0 = n0w + rr,     bx0 = brow0 & 7;
    const int brow1 = n0w + 8 + rr, bx1 = brow1 & 7;
    const int b_off0 = brow0 * 2048, b_off1 = brow1 * 2048;

    // ---- A chunk loader geometry (h stream): 2 hi + 2 lo 16B slots / thread
    const int lrow = tid >> 2;                       // 0..63
    const int lc0  = (tid & 3) * 2;                  // 0,2,4,6
    const size_t gidx = (size_t)lrow * HH + lc0 * 8; // element offset (+ck*64)
    const int sts0 = lrow * 128 + (((lc0)     ^ (lrow & 7)) << 4);
    const int sts1 = lrow * 128 + (((lc0 + 1) ^ (lrow & 7)) << 4);

    // ---- recurrent state (tid<64; row = tid)
    float c_reg[8], h_reg[8], rci[8], rcf[8], rco[8];
#pragma unroll
    for (int j = 0; j < 8; j++) { c_reg[j] = 0.0f; h_reg[j] = 0.0f; }
    if (tid < 64) {
#pragma unroll
        for (int j = 0; j < 8; j++) {
            rci[j] = wci[h0 + j]; rcf[j] = wcf[h0 + j]; rco[j] = wco[h0 + j];
        }
    }
    const int mmode = g_mask_mode;

    for (int t = 0; t < LL; ++t) {
        const __nv_bfloat16* hhi = g_hhi[t & 1];
        const __nv_bfloat16* hlo = g_hlo[t & 1];

        // prefetch x-projection + mask for the epilogue
        float gzi[8], gzf[8], gzg[8], gzo[8];
        bool mm = false;
        if (tid < 64) {
            const float* gx = g_gx + ((size_t)t * BB + tid) * GG + h0;
            *(float4*)(&gzi[0]) = *(const float4*)(gx);
            *(float4*)(&gzi[4]) = *(const float4*)(gx + 4);
            *(float4*)(&gzf[0]) = *(const float4*)(gx + 1024);
            *(float4*)(&gzf[4]) = *(const float4*)(gx + 1028);
            *(float4*)(&gzg[0]) = *(const float4*)(gx + 2048);
            *(float4*)(&gzg[4]) = *(const float4*)(gx + 2052);
            *(float4*)(&gzo[0]) = *(const float4*)(gx + 3072);
            *(float4*)(&gzo[4]) = *(const float4*)(gx + 3076);
            if (mmode == 1)      mm = (m32[tid * LL + t] != 0);
            else if (mmode == 2) mm = (mf[tid * LL + t] != 0.0f);
            else                 mm = (m8[tid * LL + t] != 0);
        }

        float d0[4] = {0.f, 0.f, 0.f, 0.f};
        float d1[4] = {0.f, 0.f, 0.f, 0.f};

        // preload chunk 0
        uint4 Rh0 = __ldcg((const uint4*)(hhi + gidx));
        uint4 Rh1 = __ldcg((const uint4*)(hhi + gidx + 8));
        uint4 Rl0 = __ldcg((const uint4*)(hlo + gidx));
        uint4 Rl1 = __ldcg((const uint4*)(hlo + gidx + 8));
        {
            char* ab = sm + SM_A;                    // buf 0
            *(uint4*)(ab + sts0)        = Rh0;
            *(uint4*)(ab + sts1)        = Rh1;
            *(uint4*)(ab + 8192 + sts0) = Rl0;
            *(uint4*)(ab + 8192 + sts1) = Rl1;
        }
        __syncthreads();

        for (int ck = 0; ck < 16; ++ck) {
            if (ck < 15) {
                size_t g = gidx + (size_t)(ck + 1) * 64;
                Rh0 = __ldcg((const uint4*)(hhi + g));
                Rh1 = __ldcg((const uint4*)(hhi + g + 8));
                Rl0 = __ldcg((const uint4*)(hlo + g));
                Rl1 = __ldcg((const uint4*)(hlo + g + 8));
            }
            const uint32_t abh = smb + SM_A + (ck & 1) * 16384;
#pragma unroll
            for (int ks = 0; ks < 4; ++ks) {
                uint32_t ah[4], al[4], bh0[2], bh1[2], bl0[2], bl1[2];
                const int ca = 2 * ks + adk;
                const uint32_t aaddr = abh + a_row_off + ((ca ^ ax) << 4);
                LDSM4(ah, aaddr);
                LDSM4(al, aaddr + 8192);
                const int cb = ck * 8 + 2 * ks + bseg;
                const uint32_t b0a = smb + SM_BHI + b_off0 + ((cb ^ bx0) << 4);
                const uint32_t b1a = smb + SM_BHI + b_off1 + ((cb ^ bx1) << 4);
                LDSM2(bh0, b0a);
                LDSM2(bh1, b1a);
                LDSM2(bl0, b0a + 65536);
                LDSM2(bl1, b1a + 65536);
                MMA16816(d0, ah, bh0); MMA16816(d1, ah, bh1);
                MMA16816(d0, al, bh0); MMA16816(d1, al, bh1);
                MMA16816(d0, ah, bl0); MMA16816(d1, ah, bl1);
            }
            if (ck < 15) {
                char* ab = sm + SM_A + ((ck + 1) & 1) * 16384;
                *(uint4*)(ab + sts0)        = Rh0;
                *(uint4*)(ab + sts1)        = Rh1;
                *(uint4*)(ab + 8192 + sts0) = Rl0;
                *(uint4*)(ab + 8192 + sts1) = Rl1;
            }
            __syncthreads();
        }

        // accumulators -> gate board
        {
            const int gid = lane >> 2, tig = lane & 3;
            const int dr0 = m0 + gid, dr1 = m0 + gid + 8;
            int cc = n0w + 2 * tig;
            *(float2*)(&Ds[dr0 * 36 + cc]) = make_float2(d0[0], d0[1]);
            *(float2*)(&Ds[dr1 * 36 + cc]) = make_float2(d0[2], d0[3]);
            cc += 8;
            *(float2*)(&Ds[dr0 * 36 + cc]) = make_float2(d1[0], d1[1]);
            *(float2*)(&Ds[dr1 * 36 + cc]) = make_float2(d1[2], d1[3]);
        }
        __syncthreads();

        // epilogue: row = tid (tid<64), owns all 4 gates of its 8 h-cols
        if (tid < 64) {
            const int row = tid;
            float hv[8];
#pragma unroll
            for (int j = 0; j < 8; j++) {
                float vi = gzi[j] + Ds[row * 36 + j];
                float vf = gzf[j] + Ds[row * 36 + 8 + j];
                float vg = gzg[j] + Ds[row * 36 + 16 + j];
                float vo = gzo[j] + Ds[row * 36 + 24 + j];
                float cold = c_reg[j];
                float iv = sigf(vi + rci[j] * cold);
                float fv = sigf(vf + rcf[j] * cold);
                float gv = tanhf_fast(vg);
                float cy = fv * cold + iv * gv;
                float ov = sigf(vo + rco[j] * cy);
                float hy = ov * tanhf_fast(cy);
                if (mm) { c_reg[j] = cy; h_reg[j] = hy; }
                hv[j] = h_reg[j];
            }
            float* op = out + ((size_t)row * LL + t) * HH + h0;
            *(float4*)(op)     = make_float4(hv[0], hv[1], hv[2], hv[3]);
            *(float4*)(op + 4) = make_float4(hv[4], hv[5], hv[6], hv[7]);

            __align__(16) __nv_bfloat16 hb[8], lb[8];
#pragma unroll
            for (int j = 0; j < 8; j++) {
                hb[j] = __float2bfloat16(hv[j]);
                lb[j] = __float2bfloat16(hv[j] - __bfloat162float(hb[j]));
            }
            *(uint4*)(&g_hhi[(t + 1) & 1][(row << 10) + h0]) = *(uint4*)hb;
            *(uint4*)(&g_hlo[(t + 1) & 1][(row << 10) + h0]) = *(uint4*)lb;

            if (t == LL - 1) {
                float* hf = out + (size_t)BB * LL * HH + row * HH + h0;
                float* cf = hf + (size_t)BB * HH;
                *(float4*)(hf)     = make_float4(hv[0], hv[1], hv[2], hv[3]);
                *(float4*)(hf + 4) = make_float4(hv[4], hv[5], hv[6], hv[7]);
                *(float4*)(cf)     = make_float4(c_reg[0], c_reg[1], c_reg[2], c_reg[3]);
                *(float4*)(cf + 4) = make_float4(c_reg[4], c_reg[5], c_reg[6], c_reg[7]);
            }
            __threadfence();       // h publish visible before barrier release
        }

        // grid-wide barrier (fresh counter per step; zeroed by init each launch)
        __syncthreads();
        if (tid == 0) {
            atomicAdd(&g_bar[t], 1u);
            while (*(volatile unsigned*)&g_bar[t] < (unsigned)gridDim.x) __nanosleep(64);
            __threadfence();
        }
        __syncthreads();
    }
}

// ---------------- launch -----------------------------------------------------
extern "C" void kernel_launch(void* const* d_in, const int* in_sizes, int n_in,
                              void* d_out, int out_size)
{
    (void)in_sizes; (void)n_in; (void)out_size;
    const float* X    = (const float*)d_in[0];
    const void*  mask = d_in[1];
    const float* Wih  = (const float*)d_in[2];
    const float* Whh  = (const float*)d_in[3];
    const float* bih  = (const float*)d_in[4];
    const float* bhh  = (const float*)d_in[5];
    const float* wci  = (const float*)d_in[6];
    const float* wcf  = (const float*)d_in[7];
    const float* wco  = (const float*)d_in[8];
    float* out = (float*)d_out;

    init_kernel<<<256, 256>>>(mask);

    dim3 g1(GG / 128, (BB * LL) / 128);
    gemm_x_kernel<<<g1, 256>>>(X, Wih, bih, bhh);

    cudaFuncSetAttribute(lstm_mma_kernel,
                         cudaFuncAttributeMaxDynamicSharedMemorySize, SMEM_TOTAL);
    lstm_mma_kernel<<<NCTA, NT, SMEM_TOTAL>>>(Whh,
                                              (const unsigned char*)mask,
                                              (const int*)mask,
                                              (const float*)mask,
                                              wci, wcf, wco, out);
}

// round 5
// speedup vs baseline: 2.4252x; 1.3566x over previous
#include <cuda_runtime.h>
#include <cuda_bf16.h>
#include <math.h>
#include <stdint.h>

#define BB 64
#define LL 1024
#define DD 512
#define HH 1024
#define GG 4096
#define NCTA 128
#define NT 256

// ---- phase-2 dynamic smem map ----
#define SM_BHI 0                      // 32 x 1024 bf16 hi (swizzled)  64KB
#define SM_BLO 65536                  // lo                            64KB
#define SM_A   131072                 // 2 bufs x (hi 16KB + lo 16KB)  64KB
#define SM_D   196608                 // 64 x 36 fp32 gate board
#define SMEM2_TOTAL (SM_D + 64 * 36 * 4)   // 205824

// ---- phase-1 dynamic smem: 2 bufs x 64KB (Ahi16 Alo16 Bhi16 Blo16) ----
#define SMEM1_TOTAL 131072

#define NX8 ((65536 * 512) / 8)       // uint4-slots of X
#define NW8 ((4096 * 512) / 8)        // uint4-slots of Wih

static __device__ float g_gx[(size_t)LL * BB * GG];   // [t][b][4H]
static __device__ __align__(16) __nv_bfloat16 g_xhi[(size_t)65536 * 512];
static __device__ __align__(16) __nv_bfloat16 g_xlo[(size_t)65536 * 512];
static __device__ __align__(16) __nv_bfloat16 g_whi[(size_t)4096 * 512];
static __device__ __align__(16) __nv_bfloat16 g_wlo[(size_t)4096 * 512];
static __device__ __align__(16) __nv_bfloat16 g_hhi[2][BB * HH];
static __device__ __align__(16) __nv_bfloat16 g_hlo[2][BB * HH];
static __device__ unsigned g_bar[LL];
static __device__ int g_mask_mode;

__device__ __forceinline__ uint32_t smem_u32(const void* p) {
    uint32_t a;
    asm("{ .reg .u64 t; cvta.to.shared.u64 t, %1; cvt.u32.u64 %0, t; }" : "=r"(a) : "l"(p));
    return a;
}
#define LDSM4(r, addr) asm volatile( \
    "ldmatrix.sync.aligned.m8n8.x4.shared.b16 {%0,%1,%2,%3}, [%4];" \
    : "=r"((r)[0]), "=r"((r)[1]), "=r"((r)[2]), "=r"((r)[3]) : "r"(addr))
#define LDSM2(r, addr) asm volatile( \
    "ldmatrix.sync.aligned.m8n8.x2.shared.b16 {%0,%1}, [%2];" \
    : "=r"((r)[0]), "=r"((r)[1]) : "r"(addr))
#define MMA16816(d, a, b) asm volatile( \
    "mma.sync.aligned.m16n8k16.row.col.f32.bf16.bf16.f32 " \
    "{%0,%1,%2,%3}, {%4,%5,%6,%7}, {%8,%9}, {%0,%1,%2,%3};" \
    : "+f"((d)[0]), "+f"((d)[1]), "+f"((d)[2]), "+f"((d)[3]) \
    : "r"((a)[0]), "r"((a)[1]), "r"((a)[2]), "r"((a)[3]), "r"((b)[0]), "r"((b)[1]))
#define CPA16(dst, src) asm volatile( \
    "cp.async.cg.shared.global [%0], [%1], 16;" :: "r"(dst), "l"(src))
#define CPCOMMIT() asm volatile("cp.async.commit_group;" ::: "memory")
#define CPWAIT0() asm volatile("cp.async.wait_group 0;" ::: "memory")

__device__ __forceinline__ float sigf(float x) { return 1.0f / (1.0f + __expf(-x)); }
__device__ __forceinline__ float tanhf_fast(float x) {
    float ax = fabsf(x);
    float e = __expf(2.0f * ax);
    float t = 1.0f - 2.0f / (e + 1.0f);
    return copysignf(t, x);
}

// ---------------- init --------------------------------------------------------
__global__ void init_kernel(const void* mask)
{
    int i = blockIdx.x * blockDim.x + threadIdx.x;
    if (i < BB * HH) {
        g_hhi[0][i] = __float2bfloat16(0.0f);
        g_hlo[0][i] = __float2bfloat16(0.0f);
    }
    if (i < LL) g_bar[i] = 0u;
    if (i == 0) {
        int v = *(const int*)mask;          // lengths >= 512 -> mask[0,0..3] true
        if (v == 1)               g_mask_mode = 1;
        else if (v == 0x3F800000) g_mask_mode = 2;
        else                      g_mask_mode = 0;
    }
}

// ---------------- prep: fp32 -> bf16 hi/lo for X and Wih ---------------------
__global__ void convert_kernel(const float* __restrict__ X, const float* __restrict__ W)
{
    size_t s = (size_t)blockIdx.x * blockDim.x + threadIdx.x;
    const float* src;
    __nv_bfloat16 *dh, *dl;
    if (s < NX8)            { src = X + s * 8; dh = g_xhi + s * 8; dl = g_xlo + s * 8; }
    else if (s < NX8 + NW8) { size_t u = s - NX8; src = W + u * 8; dh = g_whi + u * 8; dl = g_wlo + u * 8; }
    else return;
    float4 f0 = *(const float4*)(src);
    float4 f1 = *(const float4*)(src + 4);
    float v[8] = {f0.x, f0.y, f0.z, f0.w, f1.x, f1.y, f1.z, f1.w};
    __align__(16) __nv_bfloat16 hi[8], lo[8];
#pragma unroll
    for (int j = 0; j < 8; j++) {
        __nv_bfloat16 h = __float2bfloat16(v[j]);
        hi[j] = h;
        lo[j] = __float2bfloat16(v[j] - __bfloat162float(h));
    }
    *(uint4*)dh = *(uint4*)hi;
    *(uint4*)dl = *(uint4*)lo;
}

// ---------------- phase 1: g_gx = X @ Wih^T + biases (bf16 hi/lo HMMA) -------
// tile 128x128, K=512 in 8 chunks of 64. 8 warps: wm=w&1 (64 rows), wn=w>>1 (32 cols).
__global__ __launch_bounds__(256, 1)
void gemm_x_mma(const float* __restrict__ bih, const float* __restrict__ bhh)
{
    extern __shared__ __align__(16) char sm[];
    const uint32_t smb = smem_u32(sm);
    const int tid = threadIdx.x, lane = tid & 31, w = tid >> 5;
    const int wm = w & 1, wn = w >> 1;
    const int m0 = blockIdx.y * 128, n0 = blockIdx.x * 128;

    const int seg = lane >> 3, rr = lane & 7;
    const int adk = seg >> 1, bseg = seg & 1;

    // loader geometry: slot s = tid + q*256; row = s>>3, c8 = s&7
    const int lrow0 = tid >> 3, lc8 = tid & 7;
    const int soff0 = lrow0 * 128 + ((lc8 ^ (lrow0 & 7)) << 4);   // +q*4096
    const __nv_bfloat16* xh = g_xhi + (size_t)(m0 + lrow0) * DD + lc8 * 8;
    const __nv_bfloat16* xl = g_xlo + (size_t)(m0 + lrow0) * DD + lc8 * 8;
    const __nv_bfloat16* wh = g_whi + (size_t)(n0 + lrow0) * DD + lc8 * 8;
    const __nv_bfloat16* wl = g_wlo + (size_t)(n0 + lrow0) * DD + lc8 * 8;

    // per-warp LDSM row offsets (A local rows, B local rows; row stride 128B)
    int arow_off[4], brow_off[4];
#pragma unroll
    for (int mi = 0; mi < 4; mi++)
        arow_off[mi] = (wm * 64 + mi * 16 + ((seg & 1) << 3) + rr) * 128;
#pragma unroll
    for (int j = 0; j < 4; j++)
        brow_off[j] = (wn * 32 + j * 8 + rr) * 128;

    // bias (2 cols per lane per n8-tile)
    float bj0[4], bj1[4];
#pragma unroll
    for (int j = 0; j < 4; j++) {
        int col = n0 + wn * 32 + j * 8 + (lane & 3) * 2;
        bj0[j] = bih[col] + bhh[col];
        bj1[j] = bih[col + 1] + bhh[col + 1];
    }

    float acc[4][4][4];
#pragma unroll
    for (int mi = 0; mi < 4; mi++)
#pragma unroll
        for (int j = 0; j < 4; j++)
#pragma unroll
            for (int q = 0; q < 4; q++) acc[mi][j][q] = 0.0f;

    // prologue: issue chunk 0 into buf 0
    {
        uint32_t base = smb;
#pragma unroll
        for (int q = 0; q < 4; q++) {
            int go = q * 32 * DD;             // row += 32 per q
            CPA16(base + soff0 + q * 4096,         xh + go);
            CPA16(base + 16384 + soff0 + q * 4096, xl + go);
            CPA16(base + 32768 + soff0 + q * 4096, wh + go);
            CPA16(base + 49152 + soff0 + q * 4096, wl + go);
        }
        CPCOMMIT();
    }

    for (int ck = 0; ck < 8; ++ck) {
        CPWAIT0();
        __syncthreads();
        if (ck < 7) {
            uint32_t base = smb + ((ck + 1) & 1) * 65536;
            int kofs = (ck + 1) * 64;
#pragma unroll
            for (int q = 0; q < 4; q++) {
                int go = q * 32 * DD + kofs;
                CPA16(base + soff0 + q * 4096,         xh + go);
                CPA16(base + 16384 + soff0 + q * 4096, xl + go);
                CPA16(base + 32768 + soff0 + q * 4096, wh + go);
                CPA16(base + 49152 + soff0 + q * 4096, wl + go);
            }
            CPCOMMIT();
        }
        const uint32_t bufA = smb + (ck & 1) * 65536;
        const uint32_t bufB = bufA + 32768;
#pragma unroll
        for (int ks = 0; ks < 4; ++ks) {
            uint32_t ah[4][4], al[4][4], bh[4][2], bl[4][2];
            const int ca = ((2 * ks + adk) ^ rr) << 4;
            const int cb = ((2 * ks + bseg) ^ rr) << 4;
#pragma unroll
            for (int mi = 0; mi < 4; mi++) {
                LDSM4(ah[mi], bufA + arow_off[mi] + ca);
                LDSM4(al[mi], bufA + 16384 + arow_off[mi] + ca);
            }
#pragma unroll
            for (int j = 0; j < 4; j++) {
                LDSM2(bh[j], bufB + brow_off[j] + cb);
                LDSM2(bl[j], bufB + 16384 + brow_off[j] + cb);
            }
#pragma unroll
            for (int mi = 0; mi < 4; mi++)
#pragma unroll
                for (int j = 0; j < 4; j++) {
                    MMA16816(acc[mi][j], ah[mi], bh[j]);
                    MMA16816(acc[mi][j], al[mi], bh[j]);
                    MMA16816(acc[mi][j], ah[mi], bl[j]);
                }
        }
        __syncthreads();
    }

    // epilogue: + bias, write to g_gx[t][b][col]
#pragma unroll
    for (int mi = 0; mi < 4; mi++) {
        int r0 = m0 + wm * 64 + mi * 16 + (lane >> 2);
        int r1 = r0 + 8;
        float* d0 = g_gx + ((size_t)(r0 & 1023) * BB + (r0 >> 10)) * GG;
        float* d1 = g_gx + ((size_t)(r1 & 1023) * BB + (r1 >> 10)) * GG;
        int colb = n0 + wn * 32 + (lane & 3) * 2;
#pragma unroll
        for (int j = 0; j < 4; j++) {
            int col = colb + j * 8;
            *(float2*)(d0 + col) = make_float2(acc[mi][j][0] + bj0[j], acc[mi][j][1] + bj1[j]);
            *(float2*)(d1 + col) = make_float2(acc[mi][j][2] + bj0[j], acc[mi][j][3] + bj1[j]);
        }
    }
}

// ---------------- phase 2: persistent HMMA recurrence (k=128 chunks) ---------
__global__ __launch_bounds__(NT, 1)
void lstm_mma_kernel(const float* __restrict__ Whh,
                     const unsigned char* __restrict__ m8,
                     const int* __restrict__ m32,
                     const float* __restrict__ mf,
                     const float* __restrict__ wci,
                     const float* __restrict__ wcf,
                     const float* __restrict__ wco,
                     float* __restrict__ out)
{
    extern __shared__ __align__(16) char sm[];
    const uint32_t smb = smem_u32(sm);
    float* Ds = (float*)(sm + SM_D);

    const int tid  = threadIdx.x;
    const int lane = tid & 31;
    const int w    = tid >> 5;
    const int h0   = blockIdx.x * 8;

    // one-time: W slab -> smem bf16 hi/lo, 32 rows x 1024 k, swizzled (2048B rows)
    for (int s = tid; s < 4096; s += NT) {
        int n = s >> 7, c = s & 127;
        int gr = (n >> 3) * HH + h0 + (n & 7);
        const float* wp = Whh + (size_t)gr * HH + c * 8;
        __align__(16) __nv_bfloat16 hi8[8], lo8[8];
#pragma unroll
        for (int j = 0; j < 8; j++) {
            float wv = wp[j];
            __nv_bfloat16 hb = __float2bfloat16(wv);
            hi8[j] = hb;
            lo8[j] = __float2bfloat16(wv - __bfloat162float(hb));
        }
        int off = n * 2048 + ((c ^ (n & 7)) << 4);
        *(uint4*)(sm + SM_BHI + off) = *(uint4*)hi8;
        *(uint4*)(sm + SM_BLO + off) = *(uint4*)lo8;
    }
    __syncthreads();

    // per-warp mma geometry (rows: 4 tiles of 16; cols: 2 tiles of 16)
    const int m0  = (w & 3) << 4;
    const int n0w = (w >> 2) << 4;
    const int seg = lane >> 3, rr = lane & 7;
    const int arow = m0 + ((seg & 1) << 3) + rr;
    const int adk  = seg >> 1;
    const int a_row_off = arow * 256;               // 256B rows (128 k bf16)
    const int bseg  = seg & 1;
    const int b_off0 = (n0w + rr) * 2048, b_off1 = (n0w + 8 + rr) * 2048;

    // A chunk loader: slot s = tid + q*256; row = s>>4 (0..63), c = s&15
    const int lrow0 = tid >> 4, lc = tid & 15;
    const size_t gbase = (size_t)lrow0 * HH + lc * 8;       // + q*16*HH + ck*128
    const int soff = lrow0 * 256 + ((lc ^ (lrow0 & 7)) << 4);  // + q*4096

    // recurrent state (tid<64; row = tid)
    float c_reg[8], h_reg[8], rci[8], rcf[8], rco[8];
#pragma unroll
    for (int j = 0; j < 8; j++) { c_reg[j] = 0.0f; h_reg[j] = 0.0f; }
    if (tid < 64) {
#pragma unroll
        for (int j = 0; j < 8; j++) {
            rci[j] = wci[h0 + j]; rcf[j] = wcf[h0 + j]; rco[j] = wco[h0 + j];
        }
    }
    const int mmode = g_mask_mode;

    for (int t = 0; t < LL; ++t) {
        const __nv_bfloat16* hhi = g_hhi[t & 1];
        const __nv_bfloat16* hlo = g_hlo[t & 1];

        // prefetch x-projection + mask for the epilogue
        float gzi[8], gzf[8], gzg[8], gzo[8];
        bool mm = false;
        if (tid < 64) {
            const float* gx = g_gx + ((size_t)t * BB + tid) * GG + h0;
            *(float4*)(&gzi[0]) = *(const float4*)(gx);
            *(float4*)(&gzi[4]) = *(const float4*)(gx + 4);
            *(float4*)(&gzf[0]) = *(const float4*)(gx + 1024);
            *(float4*)(&gzf[4]) = *(const float4*)(gx + 1028);
            *(float4*)(&gzg[0]) = *(const float4*)(gx + 2048);
            *(float4*)(&gzg[4]) = *(const float4*)(gx + 2052);
            *(float4*)(&gzo[0]) = *(const float4*)(gx + 3072);
            *(float4*)(&gzo[4]) = *(const float4*)(gx + 3076);
            if (mmode == 1)      mm = (m32[tid * LL + t] != 0);
            else if (mmode == 2) mm = (mf[tid * LL + t] != 0.0f);
            else                 mm = (m8[tid * LL + t] != 0);
        }

        float d0[4] = {0.f, 0.f, 0.f, 0.f};
        float d1[4] = {0.f, 0.f, 0.f, 0.f};

        // preload chunk 0 (4 hi + 4 lo uint4 per thread)
        uint4 Rh[4], Rl[4];
#pragma unroll
        for (int q = 0; q < 4; q++) {
            size_t g = gbase + (size_t)q * 16 * HH;
            Rh[q] = __ldcg((const uint4*)(hhi + g));
            Rl[q] = __ldcg((const uint4*)(hlo + g));
        }
        {
            char* ab = sm + SM_A;
#pragma unroll
            for (int q = 0; q < 4; q++) {
                *(uint4*)(ab + soff + q * 4096)         = Rh[q];
                *(uint4*)(ab + 16384 + soff + q * 4096) = Rl[q];
            }
        }
        __syncthreads();

        for (int ck = 0; ck < 8; ++ck) {
            if (ck < 7) {
                size_t g0 = gbase + (size_t)(ck + 1) * 128;
#pragma unroll
                for (int q = 0; q < 4; q++) {
                    size_t g = g0 + (size_t)q * 16 * HH;
                    Rh[q] = __ldcg((const uint4*)(hhi + g));
                    Rl[q] = __ldcg((const uint4*)(hlo + g));
                }
            }
            const uint32_t abh = smb + SM_A + (ck & 1) * 32768;
#pragma unroll
            for (int ks = 0; ks < 8; ++ks) {
                uint32_t ah[4], al[4], bh0[2], bh1[2], bl0[2], bl1[2];
                const uint32_t aaddr = abh + a_row_off + (((2 * ks + adk) ^ rr) << 4);
                LDSM4(ah, aaddr);
                LDSM4(al, aaddr + 16384);
                const int cb = ((ck * 16 + 2 * ks + bseg) ^ rr) << 4;
                const uint32_t b0a = smb + SM_BHI + b_off0 + cb;
                const uint32_t b1a = smb + SM_BHI + b_off1 + cb;
                LDSM2(bh0, b0a);
                LDSM2(bh1, b1a);
                LDSM2(bl0, b0a + 65536);
                LDSM2(bl1, b1a + 65536);
                MMA16816(d0, ah, bh0); MMA16816(d1, ah, bh1);
                MMA16816(d0, al, bh0); MMA16816(d1, al, bh1);
                MMA16816(d0, ah, bl0); MMA16816(d1, ah, bl1);
            }
            if (ck < 7) {
                char* ab = sm + SM_A + ((ck + 1) & 1) * 32768;
#pragma unroll
                for (int q = 0; q < 4; q++) {
                    *(uint4*)(ab + soff + q * 4096)         = Rh[q];
                    *(uint4*)(ab + 16384 + soff + q * 4096) = Rl[q];
                }
            }
            __syncthreads();
        }

        // accumulators -> gate board
        {
            const int gid = lane >> 2, tig = lane & 3;
            const int dr0 = m0 + gid, dr1 = m0 + gid + 8;
            int cc = n0w + 2 * tig;
            *(float2*)(&Ds[dr0 * 36 + cc]) = make_float2(d0[0], d0[1]);
            *(float2*)(&Ds[dr1 * 36 + cc]) = make_float2(d0[2], d0[3]);
            cc += 8;
            *(float2*)(&Ds[dr0 * 36 + cc]) = make_float2(d1[0], d1[1]);
            *(float2*)(&Ds[dr1 * 36 + cc]) = make_float2(d1[2], d1[3]);
        }
        __syncthreads();

        // epilogue: row = tid (tid<64), owns all 4 gates of its 8 h-cols
        if (tid < 64) {
            const int row = tid;
            float hv[8];
#pragma unroll
            for (int j = 0; j < 8; j++) {
                float vi = gzi[j] + Ds[row * 36 + j];
                float vf = gzf[j] + Ds[row * 36 + 8 + j];
                float vg = gzg[j] + Ds[row * 36 + 16 + j];
                float vo = gzo[j] + Ds[row * 36 + 24 + j];
                float cold = c_reg[j];
                float iv = sigf(vi + rci[j] * cold);
                float fv = sigf(vf + rcf[j] * cold);
                float gv = tanhf_fast(vg);
                float cy = fv * cold + iv * gv;
                float ov = sigf(vo + rco[j] * cy);
                float hy = ov * tanhf_fast(cy);
                if (mm) { c_reg[j] = cy; h_reg[j] = hy; }
                hv[j] = h_reg[j];
            }
            float* op = out + ((size_t)row * LL + t) * HH + h0;
            *(float4*)(op)     = make_float4(hv[0], hv[1], hv[2], hv[3]);
            *(float4*)(op + 4) = make_float4(hv[4], hv[5], hv[6], hv[7]);

            __align__(16) __nv_bfloat16 hb[8], lb[8];
#pragma unroll
            for (int j = 0; j < 8; j++) {
                hb[j] = __float2bfloat16(hv[j]);
                lb[j] = __float2bfloat16(hv[j] - __bfloat162float(hb[j]));
            }
            *(uint4*)(&g_hhi[(t + 1) & 1][(row << 10) + h0]) = *(uint4*)hb;
            *(uint4*)(&g_hlo[(t + 1) & 1][(row << 10) + h0]) = *(uint4*)lb;

            if (t == LL - 1) {
                float* hf = out + (size_t)BB * LL * HH + row * HH + h0;
                float* cf = hf + (size_t)BB * HH;
                *(float4*)(hf)     = make_float4(hv[0], hv[1], hv[2], hv[3]);
                *(float4*)(hf + 4) = make_float4(hv[4], hv[5], hv[6], hv[7]);
                *(float4*)(cf)     = make_float4(c_reg[0], c_reg[1], c_reg[2], c_reg[3]);
                *(float4*)(cf + 4) = make_float4(c_reg[4], c_reg[5], c_reg[6], c_reg[7]);
            }
            __threadfence();
        }

        // grid-wide barrier
        __syncthreads();
        if (tid == 0) {
            atomicAdd(&g_bar[t], 1u);
            while (*(volatile unsigned*)&g_bar[t] < (unsigned)gridDim.x) __nanosleep(64);
            __threadfence();
        }
        __syncthreads();
    }
}

// ---------------- launch ------------------------------------------------------
extern "C" void kernel_launch(void* const* d_in, const int* in_sizes, int n_in,
                              void* d_out, int out_size)
{
    (void)in_sizes; (void)n_in; (void)out_size;
    const float* X    = (const float*)d_in[0];
    const void*  mask = d_in[1];
    const float* Wih  = (const float*)d_in[2];
    const float* Whh  = (const float*)d_in[3];
    const float* bih  = (const float*)d_in[4];
    const float* bhh  = (const float*)d_in[5];
    const float* wci  = (const float*)d_in[6];
    const float* wcf  = (const float*)d_in[7];
    const float* wco  = (const float*)d_in[8];
    float* out = (float*)d_out;

    init_kernel<<<256, 256>>>(mask);
    convert_kernel<<<(NX8 + NW8 + 255) / 256, 256>>>(X, Wih);

    cudaFuncSetAttribute(gemm_x_mma,
                         cudaFuncAttributeMaxDynamicSharedMemorySize, SMEM1_TOTAL);
    dim3 g1(GG / 128, (BB * LL) / 128);   // (32, 512)
    gemm_x_mma<<<g1, 256, SMEM1_TOTAL>>>(bih, bhh);

    cudaFuncSetAttribute(lstm_mma_kernel,
                         cudaFuncAttributeMaxDynamicSharedMemorySize, SMEM2_TOTAL);
    lstm_mma_kernel<<<NCTA, NT, SMEM2_TOTAL>>>(Whh,
                                               (const unsigned char*)mask,
                                               (const int*)mask,
                                               (const float*)mask,
                                               wci, wcf, wco, out);
}